// round 5
// baseline (speedup 1.0000x reference)
#include <cuda_runtime.h>
#include <cuda_fp16.h>
#include <mma.h>
#include <cstdint>

using namespace nvcuda;

#define N_NODES 100000
#define N_EDGES 640000
#define WID     128
#define NFEAT   64
#define KE      192      // WID + NFEAT
#define KM      256      // 2*WID

// ---- edge kernel smem (bytes) ----
// [0,512)    sDst int[128]
// [512,1024) sBias float[128]
// [1024, +34816)  sDiff [128][136] halves
// [35840, +67584) sC [128][132] f32 ; sFeat [128][72] halves overlays its head
#define A1_LD 136
#define A2_LD 72
#define C_LD  132
#define EK_OFF_DIFF 1024
#define EK_OFF_C    (1024 + 128*A1_LD*2)          // 35840
#define SMEM_EDGE   (EK_OFF_C + 128*C_LD*4)       // 103424 -> 2 blocks/SM

// ---- node kernel smem ----
// sX [128][136] halves | sM [128][136] halves ; sC [128][132] f32 overlays both
#define AN_LD 136
#define SMEM_NODE (2 * 128*AN_LD*2)               // 69632 -> occ 2 (reg-capped)

#define HNEG_INF2 0xFC00FC00u   // packed f16x2 (-inf, -inf)

// ---------- scratch ----------
__device__ unsigned g_maxes[(size_t)N_NODES * (WID/2)];   // 25.6 MB, f16x2 words
__device__ __half   g_We[KE * WID];
__device__ __half   g_Wm[KM * WID];

// 4-wide packed-half reduction: one 8-byte RED per lane per row
__device__ __forceinline__ void red_max_h4(unsigned* addr, unsigned v01, unsigned v23) {
    unsigned short a = (unsigned short)(v01 & 0xFFFFu);
    unsigned short b = (unsigned short)(v01 >> 16);
    unsigned short c = (unsigned short)(v23 & 0xFFFFu);
    unsigned short d = (unsigned short)(v23 >> 16);
    asm volatile("red.global.v4.f16.max.noftz [%0], {%1, %2, %3, %4};"
                 :: "l"(addr), "h"(a), "h"(b), "h"(c), "h"(d) : "memory");
}
// replace any -inf f16 half with +0
__device__ __forceinline__ unsigned fix_neginf(unsigned v) {
    if ((v & 0xFFFFu) == 0xFC00u) v &= 0xFFFF0000u;
    if ((v >> 16)     == 0xFC00u) v &= 0x0000FFFFu;
    return v;
}

// ---------- kernel 0: weights -> fp16, reset segment-max buffer ----------
__global__ void prep_kernel(const float* __restrict__ We, const float* __restrict__ Wm) {
    int i = blockIdx.x * blockDim.x + threadIdx.x;
    if (i < N_NODES * (WID/2) / 4)
        ((uint4*)g_maxes)[i] = make_uint4(HNEG_INF2, HNEG_INF2, HNEG_INF2, HNEG_INF2);
    if (i < KE * WID) g_We[i] = __float2half_rn(We[i]);
    if (i < KM * WID) g_Wm[i] = __float2half_rn(Wm[i]);
}

// ---------- kernel 1: fused edge MLP + segment-max ----------
// block = 256 threads, tile = 128 edges x 128 out, K = 192
__global__ __launch_bounds__(256, 2)
void edge_kernel(const float* __restrict__ x, const int* __restrict__ e,
                 const float* __restrict__ efeat, const float* __restrict__ b_edge) {
    extern __shared__ __align__(16) char smem[];
    int*    sDst  = (int*)smem;
    float*  sBias = (float*)(smem + 512);
    __half* sDiff = (__half*)(smem + EK_OFF_DIFF);   // [128][A1_LD]
    float*  sC    = (float*)(smem + EK_OFF_C);       // [128][C_LD]
    __half* sFeat = (__half*)(smem + EK_OFF_C);      // [128][A2_LD], dead before C stores

    const int tid  = threadIdx.x;
    const int lane = tid & 31;
    const int wid  = tid >> 5;           // 0..7
    const int ebase = blockIdx.x * 128;

    if (tid < 128) sBias[tid] = b_edge[tid];

    // front-batch edge indices (warp-uniform loads, high MLP)
    int srcs[16], dsts[16];
    #pragma unroll
    for (int it = 0; it < 16; ++it) {
        int eidx = ebase + wid * 16 + it;
        srcs[it] = e[eidx];
        dsts[it] = e[N_EDGES + eidx];
    }

    // gather: sDiff = f16(x[dst]-x[src]); sFeat = f16(e_feat)
    const float4* x4 = (const float4*)x;
    const float4* f4 = (const float4*)efeat;
    #pragma unroll 4
    for (int it = 0; it < 16; ++it) {
        int r = wid * 16 + it;
        float4 a = x4[(size_t)dsts[it] * 32 + lane];
        float4 b = x4[(size_t)srcs[it] * 32 + lane];
        __half2* drow = (__half2*)(sDiff + r * A1_LD);
        drow[lane * 2 + 0] = __floats2half2_rn(a.x - b.x, a.y - b.y);
        drow[lane * 2 + 1] = __floats2half2_rn(a.z - b.z, a.w - b.w);
        if (lane < 16) {
            float4 f = f4[(size_t)(ebase + r) * 16 + lane];
            __half2* frow = (__half2*)(sFeat + r * A2_LD);
            frow[lane * 2 + 0] = __floats2half2_rn(f.x, f.y);
            frow[lane * 2 + 1] = __floats2half2_rn(f.z, f.w);
        }
        if (lane == 0) sDst[r] = dsts[it];
    }
    __syncthreads();

    // GEMM: warp (wm, wn) computes 32x64; B fragments straight from global (L1-hot)
    const int wm = wid & 3, wn = wid >> 2;
    wmma::fragment<wmma::accumulator, 16, 16, 16, float> c[2][4];
    #pragma unroll
    for (int i = 0; i < 2; i++)
        #pragma unroll
        for (int j = 0; j < 4; j++) wmma::fill_fragment(c[i][j], 0.0f);

    #pragma unroll
    for (int k = 0; k < 12; ++k) {
        wmma::fragment<wmma::matrix_a, 16, 16, 16, __half, wmma::row_major> a[2];
        if (k < 8) {
            wmma::load_matrix_sync(a[0], sDiff + (wm * 32 +  0) * A1_LD + k * 16, A1_LD);
            wmma::load_matrix_sync(a[1], sDiff + (wm * 32 + 16) * A1_LD + k * 16, A1_LD);
        } else {
            wmma::load_matrix_sync(a[0], sFeat + (wm * 32 +  0) * A2_LD + (k - 8) * 16, A2_LD);
            wmma::load_matrix_sync(a[1], sFeat + (wm * 32 + 16) * A2_LD + (k - 8) * 16, A2_LD);
        }
        #pragma unroll
        for (int j = 0; j < 4; j++) {
            wmma::fragment<wmma::matrix_b, 16, 16, 16, __half, wmma::row_major> b;
            wmma::load_matrix_sync(b, g_We + (k * 16) * WID + wn * 64 + j * 16, WID);
            wmma::mma_sync(c[0][j], a[0], b, c[0][j]);
            wmma::mma_sync(c[1][j], a[1], b, c[1][j]);
        }
    }
    __syncthreads();   // sFeat reads complete before C overlays it

    #pragma unroll
    for (int i = 0; i < 2; i++)
        #pragma unroll
        for (int j = 0; j < 4; j++)
            wmma::store_matrix_sync(sC + (wm * 32 + i * 16) * C_LD + wn * 64 + j * 16,
                                    c[i][j], C_LD, wmma::mem_row_major);
    __syncthreads();

    // epilogue: ef = diffs + relu(C + b); segment-max via red.v4.f16
    {
        float4 bv = ((const float4*)sBias)[lane];
        #pragma unroll 4
        for (int it = 0; it < 16; ++it) {
            int m = wid * 16 + it;
            unsigned base = (unsigned)sDst[m] * 64u + lane * 2;
            const float*  crow = sC    + m * C_LD  + lane * 4;
            const __half* drow = sDiff + m * A1_LD + lane * 4;
            float v0 = fmaxf(crow[0] + bv.x, 0.0f) + __half2float(drow[0]);
            float v1 = fmaxf(crow[1] + bv.y, 0.0f) + __half2float(drow[1]);
            float v2 = fmaxf(crow[2] + bv.z, 0.0f) + __half2float(drow[2]);
            float v3 = fmaxf(crow[3] + bv.w, 0.0f) + __half2float(drow[3]);
            __half2 p0 = __floats2half2_rn(v0, v1);
            __half2 p1 = __floats2half2_rn(v2, v3);
            red_max_h4(&g_maxes[base], *(unsigned*)&p0, *(unsigned*)&p1);
        }
    }
}

// ---------- kernel 2: node MLP + residual ----------
__global__ __launch_bounds__(256, 2)
void node_kernel(const float* __restrict__ x, const float* __restrict__ b_mlp,
                 float* __restrict__ out) {
    extern __shared__ __align__(16) char smem[];
    __half* sX = (__half*)smem;                          // [128][AN_LD]
    __half* sM = (__half*)(smem + 128 * AN_LD * 2);      // [128][AN_LD]
    float*  sC = (float*)smem;                           // [128][C_LD] overlays sX+sM

    const int tid  = threadIdx.x;
    const int lane = tid & 31;
    const int wid  = tid >> 5;
    const int nbase = blockIdx.x * 128;

    // stage A: sX = f16(x), sM = maxes (already f16)
    const float4* x4 = (const float4*)x;
    #pragma unroll 4
    for (int it = 0; it < 16; ++it) {
        int r = wid * 16 + it;
        int node = nbase + r;
        __half2* arow = (__half2*)(sX + r * AN_LD);
        __half2* mrow = (__half2*)(sM + r * AN_LD);
        if (node < N_NODES) {
            float4 a = x4[(size_t)node * 32 + lane];
            arow[lane * 2 + 0] = __floats2half2_rn(a.x, a.y);
            arow[lane * 2 + 1] = __floats2half2_rn(a.z, a.w);
            uint2 mv = ((const uint2*)g_maxes)[(size_t)node * 32 + lane];
            unsigned m0 = fix_neginf(mv.x);
            unsigned m1 = fix_neginf(mv.y);
            mrow[lane * 2 + 0] = *(__half2*)&m0;
            mrow[lane * 2 + 1] = *(__half2*)&m1;
        } else {
            __half2 z = __floats2half2_rn(0.0f, 0.0f);
            arow[lane * 2 + 0] = z; arow[lane * 2 + 1] = z;
            mrow[lane * 2 + 0] = z; mrow[lane * 2 + 1] = z;
        }
    }
    __syncthreads();

    // GEMM K=256: k<8 from sX, else sM; B fragments from global (L1-hot)
    const int wm = wid & 3, wn = wid >> 2;
    wmma::fragment<wmma::accumulator, 16, 16, 16, float> c[2][4];
    #pragma unroll
    for (int i = 0; i < 2; i++)
        #pragma unroll
        for (int j = 0; j < 4; j++) wmma::fill_fragment(c[i][j], 0.0f);

    #pragma unroll
    for (int k = 0; k < 16; ++k) {
        wmma::fragment<wmma::matrix_a, 16, 16, 16, __half, wmma::row_major> a[2];
        if (k < 8) {
            wmma::load_matrix_sync(a[0], sX + (wm * 32 +  0) * AN_LD + k * 16, AN_LD);
            wmma::load_matrix_sync(a[1], sX + (wm * 32 + 16) * AN_LD + k * 16, AN_LD);
        } else {
            wmma::load_matrix_sync(a[0], sM + (wm * 32 +  0) * AN_LD + (k - 8) * 16, AN_LD);
            wmma::load_matrix_sync(a[1], sM + (wm * 32 + 16) * AN_LD + (k - 8) * 16, AN_LD);
        }
        #pragma unroll
        for (int j = 0; j < 4; j++) {
            wmma::fragment<wmma::matrix_b, 16, 16, 16, __half, wmma::row_major> b;
            wmma::load_matrix_sync(b, g_Wm + (k * 16) * WID + wn * 64 + j * 16, WID);
            wmma::mma_sync(c[0][j], a[0], b, c[0][j]);
            wmma::mma_sync(c[1][j], a[1], b, c[1][j]);
        }
    }
    __syncthreads();   // sX/sM reads complete before C overlays them

    #pragma unroll
    for (int i = 0; i < 2; i++)
        #pragma unroll
        for (int j = 0; j < 4; j++)
            wmma::store_matrix_sync(sC + (wm * 32 + i * 16) * C_LD + wn * 64 + j * 16,
                                    c[i][j], C_LD, wmma::mem_row_major);
    __syncthreads();

    // epilogue: out = x + relu(C + b_mlp); x re-read from global (coalesced, L2-hot)
    {
        float4 bv = ((const float4*)b_mlp)[lane];
        #pragma unroll 4
        for (int it = 0; it < 16; ++it) {
            int m = wid * 16 + it;
            int node = nbase + m;
            if (node >= N_NODES) continue;
            const float* crow = sC + m * C_LD + lane * 4;
            float4 xv = ((const float4*)x)[(size_t)node * 32 + lane];
            float4 o;
            o.x = xv.x + fmaxf(crow[0] + bv.x, 0.0f);
            o.y = xv.y + fmaxf(crow[1] + bv.y, 0.0f);
            o.z = xv.z + fmaxf(crow[2] + bv.z, 0.0f);
            o.w = xv.w + fmaxf(crow[3] + bv.w, 0.0f);
            ((float4*)out)[(size_t)node * 32 + lane] = o;
        }
    }
}

extern "C" void kernel_launch(void* const* d_in, const int* in_sizes, int n_in,
                              void* d_out, int out_size) {
    const float* x     = (const float*)d_in[0];
    const int*   e     = (const int*)d_in[1];
    const float* efeat = (const float*)d_in[2];
    const float* We    = (const float*)d_in[3];
    const float* be    = (const float*)d_in[4];
    const float* Wm    = (const float*)d_in[5];
    const float* bm    = (const float*)d_in[6];
    float* out = (float*)d_out;

    cudaFuncSetAttribute(edge_kernel, cudaFuncAttributeMaxDynamicSharedMemorySize, SMEM_EDGE);
    cudaFuncSetAttribute(node_kernel, cudaFuncAttributeMaxDynamicSharedMemorySize, SMEM_NODE);

    prep_kernel<<<(N_NODES * (WID/2) / 4 + 255) / 256, 256>>>(We, Wm);
    edge_kernel<<<N_EDGES / 128, 256, SMEM_EDGE>>>(x, e, efeat, be);
    node_kernel<<<(N_NODES + 127) / 128, 256, SMEM_NODE>>>(x, bm, out);
}

// round 6
// speedup vs baseline: 1.2831x; 1.2831x over previous
#include <cuda_runtime.h>
#include <cuda_fp16.h>
#include <mma.h>
#include <cstdint>

using namespace nvcuda;

#define N_NODES 100000
#define N_EDGES 640000
#define WID     128
#define NFEAT   64
#define KE      192      // WID + NFEAT
#define KM      256      // 2*WID

// ---- edge kernel smem layout (bytes) ----
#define A1_LD 136
#define A2_LD 72
#define B_LD  136
#define C_LD  132
#define SDIFF_BYTES (128*A1_LD*2)
#define SFEAT_BYTES (128*A2_LD*2)
#define SB_E_BYTES  (KE*B_LD*2)
#define SMEM_EDGE   (SDIFF_BYTES + SFEAT_BYTES + SB_E_BYTES)   // 105472 -> 2 blocks/SM

// ---- node kernel smem ----
#define A_LD_N  264
#define SMEM_NODE (128*A_LD_N*2 + KM*B_LD*2 + 128*C_LD*4)      // 204800

#define HNEG_INF2 0xFC00FC00u   // packed f16x2 (-inf, -inf)

// ---------- scratch (device globals) ----------
__device__ unsigned g_maxes[(size_t)N_NODES * (WID/2)];   // 25.6 MB, f16x2 per word
__device__ __half   g_We[KE * WID];
__device__ __half   g_Wm[KM * WID];

// 4-wide packed-half reduction: one 8-byte RED per lane per row
__device__ __forceinline__ void red_max_h4(unsigned* addr, unsigned v01, unsigned v23) {
    unsigned short a = (unsigned short)(v01 & 0xFFFFu);
    unsigned short b = (unsigned short)(v01 >> 16);
    unsigned short c = (unsigned short)(v23 & 0xFFFFu);
    unsigned short d = (unsigned short)(v23 >> 16);
    asm volatile("red.global.v4.f16.max.noftz [%0], {%1, %2, %3, %4};"
                 :: "l"(addr), "h"(a), "h"(b), "h"(c), "h"(d) : "memory");
}
// replace any -inf f16 half with +0
__device__ __forceinline__ unsigned fix_neginf(unsigned v) {
    if ((v & 0xFFFFu) == 0xFC00u) v &= 0xFFFF0000u;
    if ((v >> 16)     == 0xFC00u) v &= 0x0000FFFFu;
    return v;
}

// ---------- kernel 0: weights -> fp16, reset segment-max buffer ----------
__global__ void prep_kernel(const float* __restrict__ We, const float* __restrict__ Wm) {
    int i = blockIdx.x * blockDim.x + threadIdx.x;
    if (i < N_NODES * (WID/2) / 4)
        ((uint4*)g_maxes)[i] = make_uint4(HNEG_INF2, HNEG_INF2, HNEG_INF2, HNEG_INF2);
    if (i < KE * WID) g_We[i] = __float2half_rn(We[i]);
    if (i < KM * WID) g_Wm[i] = __float2half_rn(Wm[i]);
}

// ---------- kernel 1: fused edge MLP + segment-max ----------
// block = 256 threads, tile = 128 edges x 128 out, K = 192
__global__ __launch_bounds__(256, 2)
void edge_kernel(const float* __restrict__ x, const int* __restrict__ e,
                 const float* __restrict__ efeat, const float* __restrict__ b_edge) {
    extern __shared__ __align__(16) char smem[];
    __half* sDiff = (__half*)smem;                                // [128][A1_LD]
    __half* sFeat = (__half*)(smem + SDIFF_BYTES);                // [128][A2_LD]
    __half* sB    = (__half*)(smem + SDIFF_BYTES + SFEAT_BYTES);  // [KE][B_LD]
    float*  sC    = (float*)(smem + SDIFF_BYTES);                 // overlay [128][C_LD] -- WRONG? see below
    __shared__ int s_dst[128];

    // NOTE: C overlays sFeat+sB (both dead after GEMM); sDiff must stay live.
    sC = (float*)(smem + SDIFF_BYTES);   // sFeat start; 18432+52224 = 70656 >= 67584

    const int tid  = threadIdx.x;
    const int lane = tid & 31;
    const int wid  = tid >> 5;           // 0..7
    const int ebase = blockIdx.x * 128;

    // stage W_edge (fp16): KE*WID halves = KE*16 uint4
    {
        const uint4* gB = (const uint4*)g_We;
        for (int i = tid; i < KE * 16; i += 256) {
            int k = i >> 4, c = i & 15;
            *((uint4*)(sB + k * B_LD) + c) = gB[i];
        }
    }

    // front-batch edge indices (contiguous, high MLP)
    int srcs[16], dsts[16];
    #pragma unroll
    for (int it = 0; it < 16; ++it) {
        int eidx = ebase + wid * 16 + it;
        srcs[it] = e[eidx];
        dsts[it] = e[N_EDGES + eidx];
    }

    // stage A: sDiff = fp16(x[dst]-x[src]); sFeat = fp16(e_feat)
    const float4* x4 = (const float4*)x;
    const float4* f4 = (const float4*)efeat;
    #pragma unroll 4
    for (int it = 0; it < 16; ++it) {
        int r = wid * 16 + it;
        float4 a = x4[(size_t)dsts[it] * 32 + lane];
        float4 b = x4[(size_t)srcs[it] * 32 + lane];
        __half2* drow = (__half2*)(sDiff + r * A1_LD);
        drow[lane * 2 + 0] = __floats2half2_rn(a.x - b.x, a.y - b.y);
        drow[lane * 2 + 1] = __floats2half2_rn(a.z - b.z, a.w - b.w);
        if (lane < 16) {
            float4 f = f4[(size_t)(ebase + r) * 16 + lane];
            __half2* frow = (__half2*)(sFeat + r * A2_LD);
            frow[lane * 2 + 0] = __floats2half2_rn(f.x, f.y);
            frow[lane * 2 + 1] = __floats2half2_rn(f.z, f.w);
        }
        if (lane == 0) s_dst[r] = dsts[it];
    }
    __syncthreads();

    // GEMM: warp (wm, wn) computes 32x64; K split: diffs (8 steps) + feat (4 steps)
    const int wm = wid & 3, wn = wid >> 2;
    wmma::fragment<wmma::accumulator, 16, 16, 16, float> c[2][4];
    #pragma unroll
    for (int i = 0; i < 2; i++)
        #pragma unroll
        for (int j = 0; j < 4; j++) wmma::fill_fragment(c[i][j], 0.0f);

    #pragma unroll
    for (int k = 0; k < 12; ++k) {
        wmma::fragment<wmma::matrix_a, 16, 16, 16, __half, wmma::row_major> a[2];
        if (k < 8) {
            wmma::load_matrix_sync(a[0], sDiff + (wm * 32 +  0) * A1_LD + k * 16, A1_LD);
            wmma::load_matrix_sync(a[1], sDiff + (wm * 32 + 16) * A1_LD + k * 16, A1_LD);
        } else {
            wmma::load_matrix_sync(a[0], sFeat + (wm * 32 +  0) * A2_LD + (k - 8) * 16, A2_LD);
            wmma::load_matrix_sync(a[1], sFeat + (wm * 32 + 16) * A2_LD + (k - 8) * 16, A2_LD);
        }
        #pragma unroll
        for (int j = 0; j < 4; j++) {
            wmma::fragment<wmma::matrix_b, 16, 16, 16, __half, wmma::row_major> b;
            wmma::load_matrix_sync(b, sB + (k * 16) * B_LD + wn * 64 + j * 16, B_LD);
            wmma::mma_sync(c[0][j], a[0], b, c[0][j]);
            wmma::mma_sync(c[1][j], a[1], b, c[1][j]);
        }
    }
    __syncthreads();   // everyone done reading sFeat/sB before C overlays them

    #pragma unroll
    for (int i = 0; i < 2; i++)
        #pragma unroll
        for (int j = 0; j < 4; j++)
            wmma::store_matrix_sync(sC + (wm * 32 + i * 16) * C_LD + wn * 64 + j * 16,
                                    c[i][j], C_LD, wmma::mem_row_major);
    __syncthreads();

    // epilogue: ef = diffs + relu(C + b); segment-max via one red.v4.f16 per lane per row
    {
        float4 bv = ((const float4*)b_edge)[lane];
        #pragma unroll 4
        for (int it = 0; it < 16; ++it) {
            int m = wid * 16 + it;
            unsigned base = (unsigned)s_dst[m] * 64u + lane * 2;
            const float*  crow = sC    + m * C_LD  + lane * 4;
            const __half* drow = sDiff + m * A1_LD + lane * 4;
            float v0 = fmaxf(crow[0] + bv.x, 0.0f) + __half2float(drow[0]);
            float v1 = fmaxf(crow[1] + bv.y, 0.0f) + __half2float(drow[1]);
            float v2 = fmaxf(crow[2] + bv.z, 0.0f) + __half2float(drow[2]);
            float v3 = fmaxf(crow[3] + bv.w, 0.0f) + __half2float(drow[3]);
            __half2 p0 = __floats2half2_rn(v0, v1);
            __half2 p1 = __floats2half2_rn(v2, v3);
            red_max_h4(&g_maxes[base], *(unsigned*)&p0, *(unsigned*)&p1);
        }
    }
}

// ---------- kernel 2: node MLP + residual (round-3 config) ----------
__global__ __launch_bounds__(256, 1)
void node_kernel(const float* __restrict__ x, const float* __restrict__ b_mlp,
                 float* __restrict__ out) {
    extern __shared__ __align__(16) char smem[];
    __half* sA = (__half*)smem;                                    // [128][A_LD_N]
    __half* sB = (__half*)(smem + 128 * A_LD_N * 2);               // [KM][B_LD]
    float*  sC = (float*)(smem + 128 * A_LD_N * 2 + KM * B_LD * 2);  // [128][C_LD]

    const int tid  = threadIdx.x;
    const int lane = tid & 31;
    const int wid  = tid >> 5;
    const int nbase = blockIdx.x * 128;

    {
        const uint4* gB = (const uint4*)g_Wm;
        for (int i = tid; i < KM * 16; i += 256) {
            int k = i >> 4, c = i & 15;
            *((uint4*)(sB + k * B_LD) + c) = gB[i];
        }
    }

    const float4* x4 = (const float4*)x;
    #pragma unroll 4
    for (int it = 0; it < 16; ++it) {
        int r = wid * 16 + it;
        int node = nbase + r;
        __half2* arow = (__half2*)(sA + r * A_LD_N);
        __half2* mrow = (__half2*)(sA + r * A_LD_N + 128);
        if (node < N_NODES) {
            float4 a = x4[(size_t)node * 32 + lane];
            arow[lane * 2 + 0] = __floats2half2_rn(a.x, a.y);
            arow[lane * 2 + 1] = __floats2half2_rn(a.z, a.w);
            uint2 mv = ((const uint2*)g_maxes)[(size_t)node * 32 + lane];
            unsigned m0 = fix_neginf(mv.x);
            unsigned m1 = fix_neginf(mv.y);
            mrow[lane * 2 + 0] = *(__half2*)&m0;
            mrow[lane * 2 + 1] = *(__half2*)&m1;
        } else {
            __half2 z = __floats2half2_rn(0.0f, 0.0f);
            arow[lane * 2 + 0] = z; arow[lane * 2 + 1] = z;
            mrow[lane * 2 + 0] = z; mrow[lane * 2 + 1] = z;
        }
    }
    __syncthreads();

    {
        const int wm = wid & 3, wn = wid >> 2;
        wmma::fragment<wmma::accumulator, 16, 16, 16, float> c[2][4];
        #pragma unroll
        for (int i = 0; i < 2; i++)
            #pragma unroll
            for (int j = 0; j < 4; j++) wmma::fill_fragment(c[i][j], 0.0f);

        #pragma unroll
        for (int k = 0; k < KM / 16; ++k) {
            wmma::fragment<wmma::matrix_a, 16, 16, 16, __half, wmma::row_major> a[2];
            wmma::load_matrix_sync(a[0], sA + (wm * 32 +  0) * A_LD_N + k * 16, A_LD_N);
            wmma::load_matrix_sync(a[1], sA + (wm * 32 + 16) * A_LD_N + k * 16, A_LD_N);
            #pragma unroll
            for (int j = 0; j < 4; j++) {
                wmma::fragment<wmma::matrix_b, 16, 16, 16, __half, wmma::row_major> b;
                wmma::load_matrix_sync(b, sB + (k * 16) * B_LD + wn * 64 + j * 16, B_LD);
                wmma::mma_sync(c[0][j], a[0], b, c[0][j]);
                wmma::mma_sync(c[1][j], a[1], b, c[1][j]);
            }
        }
        #pragma unroll
        for (int i = 0; i < 2; i++)
            #pragma unroll
            for (int j = 0; j < 4; j++)
                wmma::store_matrix_sync(sC + (wm * 32 + i * 16) * C_LD + wn * 64 + j * 16,
                                        c[i][j], C_LD, wmma::mem_row_major);
    }
    __syncthreads();

    {
        float4 bv = ((const float4*)b_mlp)[lane];
        #pragma unroll 4
        for (int it = 0; it < 16; ++it) {
            int m = wid * 16 + it;
            int node = nbase + m;
            if (node >= N_NODES) continue;
            const float* crow = sC + m * C_LD + lane * 4;
            float4 xv = ((const float4*)x)[(size_t)node * 32 + lane];
            float4 o;
            o.x = xv.x + fmaxf(crow[0] + bv.x, 0.0f);
            o.y = xv.y + fmaxf(crow[1] + bv.y, 0.0f);
            o.z = xv.z + fmaxf(crow[2] + bv.z, 0.0f);
            o.w = xv.w + fmaxf(crow[3] + bv.w, 0.0f);
            ((float4*)out)[(size_t)node * 32 + lane] = o;
        }
    }
}

extern "C" void kernel_launch(void* const* d_in, const int* in_sizes, int n_in,
                              void* d_out, int out_size) {
    const float* x     = (const float*)d_in[0];
    const int*   e     = (const int*)d_in[1];
    const float* efeat = (const float*)d_in[2];
    const float* We    = (const float*)d_in[3];
    const float* be    = (const float*)d_in[4];
    const float* Wm    = (const float*)d_in[5];
    const float* bm    = (const float*)d_in[6];
    float* out = (float*)d_out;

    cudaFuncSetAttribute(edge_kernel, cudaFuncAttributeMaxDynamicSharedMemorySize, SMEM_EDGE);
    cudaFuncSetAttribute(node_kernel, cudaFuncAttributeMaxDynamicSharedMemorySize, SMEM_NODE);

    prep_kernel<<<(N_NODES * (WID/2) / 4 + 255) / 256, 256>>>(We, Wm);
    edge_kernel<<<N_EDGES / 128, 256, SMEM_EDGE>>>(x, e, efeat, be);
    node_kernel<<<(N_NODES + 127) / 128, 256, SMEM_NODE>>>(x, bm, out);
}

// round 7
// speedup vs baseline: 1.3400x; 1.0443x over previous
#include <cuda_runtime.h>
#include <cuda_fp16.h>
#include <mma.h>
#include <cstdint>

using namespace nvcuda;

#define N_NODES 100000
#define N_EDGES 640000
#define WID     128
#define NFEAT   64
#define KE      192      // WID + NFEAT
#define KM      256      // 2*WID

// ---- edge kernel smem layout (bytes) ----
#define A1_LD 136
#define A2_LD 72
#define B_LD  136
#define C_LD  132
#define SDIFF_BYTES (128*A1_LD*2)
#define SFEAT_BYTES (128*A2_LD*2)
#define SB_E_BYTES  (KE*B_LD*2)
#define SMEM_EDGE   (SDIFF_BYTES + SFEAT_BYTES + SB_E_BYTES)   // 105472 -> 2 blocks/SM

// ---- node kernel smem: sA [128][264]h (sC overlays) + sB chunk [128][136]h ----
#define A_LD_N  264
#define SA_N_BYTES (128*A_LD_N*2)                 // 67584 (== 128*C_LD*4, exact C overlay)
#define SMEM_NODE (SA_N_BYTES + 128*B_LD*2)       // 102400 -> 2 blocks/SM

#define HNEG_INF2 0xFC00FC00u   // packed f16x2 (-inf, -inf)

// ---------- scratch (device globals) ----------
__device__ unsigned g_maxes[(size_t)N_NODES * (WID/2)];   // 25.6 MB, f16x2 per word
__device__ __align__(16) __half g_xh[(size_t)N_NODES * WID];  // 25.6 MB fp16 x image
__device__ __half   g_We[KE * WID];
__device__ __half   g_Wm[KM * WID];

// 4-wide packed-half reduction: one 8-byte RED per lane per row
__device__ __forceinline__ void red_max_h4(unsigned* addr, unsigned v01, unsigned v23) {
    unsigned short a = (unsigned short)(v01 & 0xFFFFu);
    unsigned short b = (unsigned short)(v01 >> 16);
    unsigned short c = (unsigned short)(v23 & 0xFFFFu);
    unsigned short d = (unsigned short)(v23 >> 16);
    asm volatile("red.global.v4.f16.max.noftz [%0], {%1, %2, %3, %4};"
                 :: "l"(addr), "h"(a), "h"(b), "h"(c), "h"(d) : "memory");
}
// replace any -inf f16 half with +0
__device__ __forceinline__ unsigned fix_neginf(unsigned v) {
    if ((v & 0xFFFFu) == 0xFC00u) v &= 0xFFFF0000u;
    if ((v >> 16)     == 0xFC00u) v &= 0x0000FFFFu;
    return v;
}

// ---------- kernel 0: weights+x -> fp16, reset segment-max buffer ----------
__global__ void prep_kernel(const float* __restrict__ x,
                            const float* __restrict__ We, const float* __restrict__ Wm) {
    int i = blockIdx.x * blockDim.x + threadIdx.x;
    // x -> fp16 image: 3.2M float4 -> uint2
    if (i < N_NODES * WID / 4) {
        float4 v = ((const float4*)x)[i];
        __half2 h0 = __floats2half2_rn(v.x, v.y);
        __half2 h1 = __floats2half2_rn(v.z, v.w);
        ((uint2*)g_xh)[i] = make_uint2(*(unsigned*)&h0, *(unsigned*)&h1);
    }
    // maxes init: 1.6M uint4
    if (i < N_NODES * (WID/2) / 4)
        ((uint4*)g_maxes)[i] = make_uint4(HNEG_INF2, HNEG_INF2, HNEG_INF2, HNEG_INF2);
    if (i < KE * WID) g_We[i] = __float2half_rn(We[i]);
    if (i < KM * WID) g_Wm[i] = __float2half_rn(Wm[i]);
}

// ---------- kernel 1: fused edge MLP + segment-max ----------
// block = 256 threads, tile = 128 edges x 128 out, K = 192
__global__ __launch_bounds__(256, 2)
void edge_kernel(const int* __restrict__ e, const float* __restrict__ efeat,
                 const float* __restrict__ b_edge) {
    extern __shared__ __align__(16) char smem[];
    __half* sDiff = (__half*)smem;                                // [128][A1_LD]
    __half* sFeat = (__half*)(smem + SDIFF_BYTES);                // [128][A2_LD]
    __half* sB    = (__half*)(smem + SDIFF_BYTES + SFEAT_BYTES);  // [KE][B_LD]
    float*  sC    = (float*)(smem + SDIFF_BYTES);                 // overlays sFeat+sB (dead post-GEMM)
    __shared__ int s_dst[128];

    const int tid  = threadIdx.x;
    const int lane = tid & 31;
    const int wid  = tid >> 5;           // 0..7
    const int ebase = blockIdx.x * 128;

    // stage W_edge (fp16): KE*WID halves = KE*16 uint4
    {
        const uint4* gB = (const uint4*)g_We;
        for (int i = tid; i < KE * 16; i += 256) {
            int k = i >> 4, c = i & 15;
            *((uint4*)(sB + k * B_LD) + c) = gB[i];
        }
    }

    // front-batch edge indices (contiguous, high MLP)
    int srcs[16], dsts[16];
    #pragma unroll
    for (int it = 0; it < 16; ++it) {
        int eidx = ebase + wid * 16 + it;
        srcs[it] = e[eidx];
        dsts[it] = e[N_EDGES + eidx];
    }

    // gather: sDiff = xh[dst]-xh[src] (fp16); sFeat = fp16(e_feat)
    const uint2*  xh = (const uint2*)g_xh;       // 32 uint2 per row
    const float4* f4 = (const float4*)efeat;
    #pragma unroll 4
    for (int it = 0; it < 16; ++it) {
        int r = wid * 16 + it;
        uint2 a = xh[(size_t)dsts[it] * 32 + lane];
        uint2 b = xh[(size_t)srcs[it] * 32 + lane];
        __half2 d0 = __hsub2(*(__half2*)&a.x, *(__half2*)&b.x);
        __half2 d1 = __hsub2(*(__half2*)&a.y, *(__half2*)&b.y);
        *(uint2*)(sDiff + r * A1_LD + lane * 4) =
            make_uint2(*(unsigned*)&d0, *(unsigned*)&d1);
        if (lane < 16) {
            float4 f = f4[(size_t)(ebase + r) * 16 + lane];
            __half2* frow = (__half2*)(sFeat + r * A2_LD);
            frow[lane * 2 + 0] = __floats2half2_rn(f.x, f.y);
            frow[lane * 2 + 1] = __floats2half2_rn(f.z, f.w);
        }
        if (lane == 0) s_dst[r] = dsts[it];
    }
    __syncthreads();

    // GEMM: warp (wm, wn) computes 32x64; K split: diffs (8 steps) + feat (4 steps)
    const int wm = wid & 3, wn = wid >> 2;
    wmma::fragment<wmma::accumulator, 16, 16, 16, float> c[2][4];
    #pragma unroll
    for (int i = 0; i < 2; i++)
        #pragma unroll
        for (int j = 0; j < 4; j++) wmma::fill_fragment(c[i][j], 0.0f);

    #pragma unroll
    for (int k = 0; k < 12; ++k) {
        wmma::fragment<wmma::matrix_a, 16, 16, 16, __half, wmma::row_major> a[2];
        if (k < 8) {
            wmma::load_matrix_sync(a[0], sDiff + (wm * 32 +  0) * A1_LD + k * 16, A1_LD);
            wmma::load_matrix_sync(a[1], sDiff + (wm * 32 + 16) * A1_LD + k * 16, A1_LD);
        } else {
            wmma::load_matrix_sync(a[0], sFeat + (wm * 32 +  0) * A2_LD + (k - 8) * 16, A2_LD);
            wmma::load_matrix_sync(a[1], sFeat + (wm * 32 + 16) * A2_LD + (k - 8) * 16, A2_LD);
        }
        #pragma unroll
        for (int j = 0; j < 4; j++) {
            wmma::fragment<wmma::matrix_b, 16, 16, 16, __half, wmma::row_major> b;
            wmma::load_matrix_sync(b, sB + (k * 16) * B_LD + wn * 64 + j * 16, B_LD);
            wmma::mma_sync(c[0][j], a[0], b, c[0][j]);
            wmma::mma_sync(c[1][j], a[1], b, c[1][j]);
        }
    }
    __syncthreads();   // everyone done reading sFeat/sB before C overlays them

    #pragma unroll
    for (int i = 0; i < 2; i++)
        #pragma unroll
        for (int j = 0; j < 4; j++)
            wmma::store_matrix_sync(sC + (wm * 32 + i * 16) * C_LD + wn * 64 + j * 16,
                                    c[i][j], C_LD, wmma::mem_row_major);
    __syncthreads();

    // epilogue: ef = diffs + relu(C + b); one red.v4.f16 per lane per row
    {
        float4 bv = ((const float4*)b_edge)[lane];
        #pragma unroll 4
        for (int it = 0; it < 16; ++it) {
            int m = wid * 16 + it;
            unsigned base = (unsigned)s_dst[m] * 64u + lane * 2;
            const float*  crow = sC    + m * C_LD  + lane * 4;
            const __half* drow = sDiff + m * A1_LD + lane * 4;
            float v0 = fmaxf(crow[0] + bv.x, 0.0f) + __half2float(drow[0]);
            float v1 = fmaxf(crow[1] + bv.y, 0.0f) + __half2float(drow[1]);
            float v2 = fmaxf(crow[2] + bv.z, 0.0f) + __half2float(drow[2]);
            float v3 = fmaxf(crow[3] + bv.w, 0.0f) + __half2float(drow[3]);
            __half2 p0 = __floats2half2_rn(v0, v1);
            __half2 p1 = __floats2half2_rn(v2, v3);
            red_max_h4(&g_maxes[base], *(unsigned*)&p0, *(unsigned*)&p1);
        }
    }
}

// ---------- kernel 2: node MLP + residual (split-K B staging -> occ 2) ----------
__global__ __launch_bounds__(256, 2)
void node_kernel(const float* __restrict__ x, const float* __restrict__ b_mlp,
                 float* __restrict__ out) {
    extern __shared__ __align__(16) char smem[];
    __half* sA = (__half*)smem;                      // [128][A_LD_N]
    __half* sB = (__half*)(smem + SA_N_BYTES);       // [128][B_LD] (one K-chunk)
    float*  sC = (float*)smem;                       // [128][C_LD] overlays sA (dead post-GEMM)

    const int tid  = threadIdx.x;
    const int lane = tid & 31;
    const int wid  = tid >> 5;
    const int nbase = blockIdx.x * 128;
    const int wm = wid & 3, wn = wid >> 2;

    // stage B chunk 0 (W_mlp rows 0..127)
    {
        const uint4* gB = (const uint4*)g_Wm;
        for (int i = tid; i < 128 * 16; i += 256) {
            int k = i >> 4, c = i & 15;
            *((uint4*)(sB + k * B_LD) + c) = gB[i];
        }
    }

    // stage A: cols 0..127 = xh (fp16 image), 128..255 = maxes (fp16)
    const uint2* xh = (const uint2*)g_xh;
    #pragma unroll 4
    for (int it = 0; it < 16; ++it) {
        int r = wid * 16 + it;
        int node = nbase + r;
        if (node < N_NODES) {
            *(uint2*)(sA + r * A_LD_N + lane * 4) = xh[(size_t)node * 32 + lane];
            uint2 mv = ((const uint2*)g_maxes)[(size_t)node * 32 + lane];
            *(uint2*)(sA + r * A_LD_N + 128 + lane * 4) =
                make_uint2(fix_neginf(mv.x), fix_neginf(mv.y));
        } else {
            *(uint2*)(sA + r * A_LD_N + lane * 4) = make_uint2(0u, 0u);
            *(uint2*)(sA + r * A_LD_N + 128 + lane * 4) = make_uint2(0u, 0u);
        }
    }
    __syncthreads();

    wmma::fragment<wmma::accumulator, 16, 16, 16, float> c[2][4];
    #pragma unroll
    for (int i = 0; i < 2; i++)
        #pragma unroll
        for (int j = 0; j < 4; j++) wmma::fill_fragment(c[i][j], 0.0f);

    // GEMM chunk 0: A cols 0..127 (x part), B chunk 0
    #pragma unroll
    for (int k = 0; k < 8; ++k) {
        wmma::fragment<wmma::matrix_a, 16, 16, 16, __half, wmma::row_major> a[2];
        wmma::load_matrix_sync(a[0], sA + (wm * 32 +  0) * A_LD_N + k * 16, A_LD_N);
        wmma::load_matrix_sync(a[1], sA + (wm * 32 + 16) * A_LD_N + k * 16, A_LD_N);
        #pragma unroll
        for (int j = 0; j < 4; j++) {
            wmma::fragment<wmma::matrix_b, 16, 16, 16, __half, wmma::row_major> b;
            wmma::load_matrix_sync(b, sB + (k * 16) * B_LD + wn * 64 + j * 16, B_LD);
            wmma::mma_sync(c[0][j], a[0], b, c[0][j]);
            wmma::mma_sync(c[1][j], a[1], b, c[1][j]);
        }
    }
    __syncthreads();   // chunk-0 reads done

    // stage B chunk 1 (W_mlp rows 128..255)
    {
        const uint4* gB = (const uint4*)g_Wm + 128 * 16;
        for (int i = tid; i < 128 * 16; i += 256) {
            int k = i >> 4, c = i & 15;
            *((uint4*)(sB + k * B_LD) + c) = gB[i];
        }
    }
    __syncthreads();

    // GEMM chunk 1: A cols 128..255 (maxes part), B chunk 1
    #pragma unroll
    for (int k = 0; k < 8; ++k) {
        wmma::fragment<wmma::matrix_a, 16, 16, 16, __half, wmma::row_major> a[2];
        wmma::load_matrix_sync(a[0], sA + (wm * 32 +  0) * A_LD_N + 128 + k * 16, A_LD_N);
        wmma::load_matrix_sync(a[1], sA + (wm * 32 + 16) * A_LD_N + 128 + k * 16, A_LD_N);
        #pragma unroll
        for (int j = 0; j < 4; j++) {
            wmma::fragment<wmma::matrix_b, 16, 16, 16, __half, wmma::row_major> b;
            wmma::load_matrix_sync(b, sB + (k * 16) * B_LD + wn * 64 + j * 16, B_LD);
            wmma::mma_sync(c[0][j], a[0], b, c[0][j]);
            wmma::mma_sync(c[1][j], a[1], b, c[1][j]);
        }
    }
    __syncthreads();   // sA reads done before C overlays it

    #pragma unroll
    for (int i = 0; i < 2; i++)
        #pragma unroll
        for (int j = 0; j < 4; j++)
            wmma::store_matrix_sync(sC + (wm * 32 + i * 16) * C_LD + wn * 64 + j * 16,
                                    c[i][j], C_LD, wmma::mem_row_major);
    __syncthreads();

    // epilogue: out = x + relu(C + b_mlp); residual from original f32 x
    {
        float4 bv = ((const float4*)b_mlp)[lane];
        #pragma unroll 4
        for (int it = 0; it < 16; ++it) {
            int m = wid * 16 + it;
            int node = nbase + m;
            if (node >= N_NODES) continue;
            const float* crow = sC + m * C_LD + lane * 4;
            float4 xv = ((const float4*)x)[(size_t)node * 32 + lane];
            float4 o;
            o.x = xv.x + fmaxf(crow[0] + bv.x, 0.0f);
            o.y = xv.y + fmaxf(crow[1] + bv.y, 0.0f);
            o.z = xv.z + fmaxf(crow[2] + bv.z, 0.0f);
            o.w = xv.w + fmaxf(crow[3] + bv.w, 0.0f);
            ((float4*)out)[(size_t)node * 32 + lane] = o;
        }
    }
}

extern "C" void kernel_launch(void* const* d_in, const int* in_sizes, int n_in,
                              void* d_out, int out_size) {
    const float* x     = (const float*)d_in[0];
    const int*   e     = (const int*)d_in[1];
    const float* efeat = (const float*)d_in[2];
    const float* We    = (const float*)d_in[3];
    const float* be    = (const float*)d_in[4];
    const float* Wm    = (const float*)d_in[5];
    const float* bm    = (const float*)d_in[6];
    float* out = (float*)d_out;

    cudaFuncSetAttribute(edge_kernel, cudaFuncAttributeMaxDynamicSharedMemorySize, SMEM_EDGE);
    cudaFuncSetAttribute(node_kernel, cudaFuncAttributeMaxDynamicSharedMemorySize, SMEM_NODE);

    prep_kernel<<<(N_NODES * WID / 4 + 255) / 256, 256>>>(x, We, Wm);
    edge_kernel<<<N_EDGES / 128, 256, SMEM_EDGE>>>(e, efeat, be);
    node_kernel<<<(N_NODES + 127) / 128, 256, SMEM_NODE>>>(x, bm, out);
}